// round 11
// baseline (speedup 1.0000x reference)
#include <cuda_runtime.h>
#include <cuda_bf16.h>

// LSTMStateBufferCell:
//   pos[b]  = sum_s hidden_masks[s,b]            (pos in [0,S])
//   prev    = mod(pos-1, S+1)
//   stack_X = [init_X ; X]  (index 0 = init row)
//   out_h[b,:] = stack_h[prev]*a + stack_h[pos]*(1-a),  a = |op[b]|
//   out_c[b,:] = stack_c[prev]*a + stack_c[pos]*(1-a)
// Output layout: f32 [2, B, H] (hidden then cell).
//
// BARRIER-FREE fast path (S==1024, H==1024): one block per batch element,
// 512 threads = 16 warps. Every warp redundantly computes the FULL column
// sum (32 loads/lane, high MLP, mostly cache hits after first touch) and
// finishes with one REDUX.SUM — no shared memory, no __syncthreads anywhere.
// Each warp proceeds to its own gather+store the moment its own sum resolves,
// removing the slowest-warp barrier wait from the critical path.
// Copy mapping: warps 0-7 -> hidden, 8-15 -> cell; each warp's 32 lanes write
// one float4 each: 16*32*4 = 2048 floats = 2*H exactly.
// a in {0,1} => pure row select; general blend fallback preserved.

#define NTH 512

__global__ __launch_bounds__(NTH)
void lstm_state_kernel_fast(
    const float* __restrict__ hiddens,
    const float* __restrict__ cells,
    const float* __restrict__ init_hidden,
    const float* __restrict__ init_cell,
    const int*   __restrict__ masks,
    const int*   __restrict__ op,
    float* __restrict__ out,
    int S, int B, int H)     // S==1024, H==1024
{
    const int b   = blockIdx.x;
    const int tid = threadIdx.x;
    const int lid = tid & 31;
    const int wid = tid >> 5;            // 0..15

    // Independent of the mask chain — issue first.
    const float a  = fabsf((float)op[b]);
    const float na = 1.0f - a;

    // ---- pos[b]: every warp computes the full column sum independently ----
    // lane l covers rows {l, l+32, l+64, ...}: 32 loads, all independent (MLP=32).
    const int* colp = masks + b;         // column b, row stride B ints
    int local = 0;
    #pragma unroll
    for (int k = 0; k < 32; k++)
        local += colp[(size_t)(lid + (k << 5)) * B];

    // One-instruction warp reduction; every lane gets pos. No smem, no BAR.
    const int pos  = __reduce_add_sync(0xffffffffu, local);
    const int prev = (pos == 0) ? S : pos - 1;   // mod(pos-1, S+1)

    // ---- Row select / blend: warp-private, no synchronization ----
    const size_t rowstride = (size_t)B * H;
    const int half = wid >> 3;           // 0 = hidden (warps 0-7), 1 = cell
    const int i    = ((wid & 7) << 5) + lid;   // float4 index in [0,256) == H/4

    const float* data  = half ? cells     : hiddens;
    const float* initv = half ? init_cell : init_hidden;

    const float4* c4 = (const float4*)((pos  == 0) ? initv
                        : data + (size_t)(pos  - 1) * rowstride + (size_t)b * H);
    const float4* p4 = (const float4*)((prev == 0) ? initv
                        : data + (size_t)(prev - 1) * rowstride + (size_t)b * H);
    float4* d4 = (float4*)(out + (size_t)half * rowstride + (size_t)b * H);

    if (a == 1.0f) {
        d4[i] = p4[i];
    } else if (a == 0.0f) {
        d4[i] = c4[i];
    } else {
        float4 vp = p4[i], vc = c4[i], r;
        r.x = vp.x * a + vc.x * na;
        r.y = vp.y * a + vc.y * na;
        r.z = vp.z * a + vc.z * na;
        r.w = vp.w * a + vc.w * na;
        d4[i] = r;
    }
}

// ---------------- Generic fallback (any S,B,H) ----------------
__global__ __launch_bounds__(NTH)
void lstm_state_kernel_generic(
    const float* __restrict__ hiddens,
    const float* __restrict__ cells,
    const float* __restrict__ init_hidden,
    const float* __restrict__ init_cell,
    const int*   __restrict__ masks,
    const int*   __restrict__ op,
    float* __restrict__ out,
    int S, int B, int H)
{
    const int b   = blockIdx.x;
    const int tid = threadIdx.x;

    const float a  = fabsf((float)op[b]);
    const float na = 1.0f - a;

    int local = 0;
    for (int s = tid; s < S; s += NTH)
        local += masks[(size_t)s * B + b];

    local = __reduce_add_sync(0xffffffffu, local);

    __shared__ int wsum[NTH / 32];
    if ((tid & 31) == 0) wsum[tid >> 5] = local;
    __syncthreads();

    int pos = 0;
    #pragma unroll
    for (int w = 0; w < NTH / 32; w++) pos += wsum[w];

    const int prev = (pos == 0) ? S : pos - 1;

    const size_t rowstride = (size_t)B * H;
    const int half = tid >> 8;
    const int lane = tid & 255;

    const float* data  = half ? cells     : hiddens;
    const float* initv = half ? init_cell : init_hidden;
    const float* cur_row  = (pos  == 0) ? initv
                          : data + (size_t)(pos  - 1) * rowstride + (size_t)b * H;
    const float* prev_row = (prev == 0) ? initv
                          : data + (size_t)(prev - 1) * rowstride + (size_t)b * H;
    float* dst = out + (size_t)half * rowstride + (size_t)b * H;

    for (int i = lane; i < H; i += 256)
        dst[i] = prev_row[i] * a + cur_row[i] * na;
}

extern "C" void kernel_launch(void* const* d_in, const int* in_sizes, int n_in,
                              void* d_out, int out_size)
{
    const float* hiddens     = (const float*)d_in[0];
    const float* cells       = (const float*)d_in[1];
    const float* init_hidden = (const float*)d_in[2];
    const float* init_cell   = (const float*)d_in[3];
    const int*   masks       = (const int*)d_in[4];
    const int*   op          = (const int*)d_in[5];
    float*       out         = (float*)d_out;

    const int H = in_sizes[2];          // init_hidden length
    const int B = in_sizes[5];          // op length
    const int S = in_sizes[4] / B;      // masks is [S,B]

    if (S == 1024 && H == 1024) {
        lstm_state_kernel_fast<<<B, NTH>>>(hiddens, cells, init_hidden, init_cell,
                                           masks, op, out, S, B, H);
    } else {
        lstm_state_kernel_generic<<<B, NTH>>>(hiddens, cells, init_hidden, init_cell,
                                              masks, op, out, S, B, H);
    }
}

// round 12
// speedup vs baseline: 1.8605x; 1.8605x over previous
#include <cuda_runtime.h>
#include <cuda_bf16.h>

// LSTMStateBufferCell:
//   pos[b]  = sum_s hidden_masks[s,b]            (pos in [0,S])
//   prev    = mod(pos-1, S+1)
//   stack_X = [init_X ; X]  (index 0 = init row)
//   out_h[b,:] = stack_h[prev]*a + stack_h[pos]*(1-a),  a = |op[b]|
//   out_c[b,:] = stack_c[prev]*a + stack_c[pos]*(1-a)
// Output layout: f32 [2, B, H] (hidden then cell).
//
// Final configuration (best-evidenced across 11 rounds): one block per batch
// element, 512 threads, everything recomputed every call.
//   - mask reduce: strided LDGs (2/thread for S=1024 -> minimal L1tex
//     wavefront count: each line touched exactly once per block)
//     -> one REDUX.SUM -> ONE __syncthreads -> serial sum of 16 warp partials.
//   - copy: threads 0-255 -> hidden, 256-511 -> cell; exactly one float4
//     load + one float4 store per thread for H==1024. a in {0,1} => pure row
//     select; general blend fallback preserved for any a.
// Round-11 lesson encoded here: do NOT replicate strided mask loads per warp
// (L1tex wavefront serialization costs ~6us); one pass + one barrier is
// strictly better. dur_us is pinned at the ~6.6us graph-replay floor.

#define NTH 512

__global__ __launch_bounds__(NTH)
void lstm_state_kernel(
    const float* __restrict__ hiddens,
    const float* __restrict__ cells,
    const float* __restrict__ init_hidden,
    const float* __restrict__ init_cell,
    const int*   __restrict__ masks,
    const int*   __restrict__ op,
    float* __restrict__ out,
    int S, int B, int H)
{
    const int b   = blockIdx.x;
    const int tid = threadIdx.x;

    // Independent of the mask chain — issue first.
    const float a  = fabsf((float)op[b]);
    const float na = 1.0f - a;

    // ---- pos[b] = sum over the mask column (each line touched once) ----
    int local = 0;
    for (int s = tid; s < S; s += NTH)
        local += masks[(size_t)s * B + b];

    // One-instruction warp reduction (REDUX.SUM).
    local = __reduce_add_sync(0xffffffffu, local);

    __shared__ int wsum[NTH / 32];
    if ((tid & 31) == 0) wsum[tid >> 5] = local;
    __syncthreads();

    // Single-stage finish: every thread sums the 16 warp partials serially.
    int pos = 0;
    #pragma unroll
    for (int w = 0; w < NTH / 32; w++) pos += wsum[w];

    const int prev = (pos == 0) ? S : pos - 1;   // mod(pos-1, S+1)

    // ---- Row select / blend ----
    const size_t rowstride = (size_t)B * H;

    // Thread role: lower half of the block -> hidden, upper half -> cell.
    const int half = tid >> 8;           // 0 = hidden, 1 = cell
    const int lane = tid & 255;

    const float* data  = half ? cells     : hiddens;
    const float* initv = half ? init_cell : init_hidden;

    const float* cur_row  = (pos  == 0) ? initv
                          : data + (size_t)(pos  - 1) * rowstride + (size_t)b * H;
    const float* prev_row = (prev == 0) ? initv
                          : data + (size_t)(prev - 1) * rowstride + (size_t)b * H;
    float* dst = out + (size_t)half * rowstride + (size_t)b * H;

    if ((H & 3) == 0) {
        const int H4 = H >> 2;           // 256 for H=1024 -> exactly 1 iter/thread
        const float4* c4 = (const float4*)cur_row;
        const float4* p4 = (const float4*)prev_row;
        float4* d4 = (float4*)dst;

        if (a == 1.0f) {
            for (int i = lane; i < H4; i += 256) d4[i] = p4[i];
        } else if (a == 0.0f) {
            for (int i = lane; i < H4; i += 256) d4[i] = c4[i];
        } else {
            for (int i = lane; i < H4; i += 256) {
                float4 vp = p4[i], vc = c4[i], r;
                r.x = vp.x * a + vc.x * na;
                r.y = vp.y * a + vc.y * na;
                r.z = vp.z * a + vc.z * na;
                r.w = vp.w * a + vc.w * na;
                d4[i] = r;
            }
        }
    } else {
        for (int i = lane; i < H; i += 256)
            dst[i] = prev_row[i] * a + cur_row[i] * na;
    }
}

extern "C" void kernel_launch(void* const* d_in, const int* in_sizes, int n_in,
                              void* d_out, int out_size)
{
    const float* hiddens     = (const float*)d_in[0];
    const float* cells       = (const float*)d_in[1];
    const float* init_hidden = (const float*)d_in[2];
    const float* init_cell   = (const float*)d_in[3];
    const int*   masks       = (const int*)d_in[4];
    const int*   op          = (const int*)d_in[5];
    float*       out         = (float*)d_out;

    const int H = in_sizes[2];          // init_hidden length
    const int B = in_sizes[5];          // op length
    const int S = in_sizes[4] / B;      // masks is [S,B]

    lstm_state_kernel<<<B, NTH>>>(hiddens, cells, init_hidden, init_cell,
                                  masks, op, out, S, B, H);
}